// round 10
// baseline (speedup 1.0000x reference)
#include <cuda_runtime.h>

// ---------------------------------------------------------------------------
// Single fused kernel. out[p] = prod_l (1 - V[l,p]) * poly(p), V pseudo-Voigt.
// CTA = 676-px chunk (grid = 148 = one wave), BLOCK = 896 (28 warps).
//
// Hierarchy:
//  CTA-far  (> 20 A): linearized lorentz at 4 chunk nodes (cubic), inline in
//           the stream pass with batched rcp; reduction lane-parallel.
//  CTA-mid  (4..20 A): 16 uniform nodes (piecewise cubic), warp w -> node w.
//  chunk-near, per warp: warp-near (<= 4 A of warp span) exact voigt;
//           warp-mid (rest) lorentz at 3 warp nodes, quadratic interp.
//
// R10: slot-addressed stash (slot = l & 255; window ~83 consecutive sorted
// lines << 256, no aliasing) replaces per-line boundary cmp/sel chains and
// block-wide atomicMax index discovery; only stashing threads do shared
// atomicMin/Max to publish [alo,ahi) and [nlo,nhi).
// ---------------------------------------------------------------------------

#define BLOCK     896
#define NWARPS    28
#define CHUNK     676
#define NWIN      4.0f
#define AWIN      20.0f
#define WNWIN     4.0f
#define STASH     256
#define SMASK     255
#define LOG2E     1.4426950408889634f
#define FULLM     0xFFFFFFFFu

__device__ __forceinline__ float frcp(float x) {
    float r; asm("rcp.approx.ftz.f32 %0, %1;" : "=f"(r) : "f"(x)); return r;
}
__device__ __forceinline__ float fex2(float x) {
    float r; asm("ex2.approx.ftz.f32 %0, %1;" : "=f"(r) : "f"(x)); return r;
}
__device__ __forceinline__ float flg2(float x) {
    float r; asm("lg2.approx.ftz.f32 %0, %1;" : "=f"(r) : "f"(x)); return r;
}

__global__ void __launch_bounds__(BLOCK)
fused_kernel(const float* __restrict__ wl, int npix, int L,
             const float* __restrict__ lam,
             const float* __restrict__ amps,
             const float* __restrict__ sw,
             const float* __restrict__ gw,
             const float* __restrict__ pa,
             const float* __restrict__ pb,
             const float* __restrict__ pc,
             float* __restrict__ out) {
    __shared__ float4 sA[STASH];             // slot l&255: {lam, g^2, c_lor, m}
    __shared__ float  sB[STASH];             // c_gauss
    __shared__ float  sWredF[4 * NWARPS];
    __shared__ float  sS[4];
    __shared__ float  sMid[16];
    __shared__ int    sIdx[4];               // {min l, max l, min nl, max nl}

    const int tid  = threadIdx.x;
    const int w    = tid >> 5, lane = tid & 31;
    const int p0   = blockIdx.x * CHUNK;
    const int cnt  = min(CHUNK, npix - p0);
    const int p    = p0 + tid;
    const float wlp = wl[min(p, npix - 1)];

    const float wlLo = wl[p0];
    const float wlHi = wl[p0 + cnt - 1];
    const float span = wlHi - wlLo;
    const float b0 = wlLo - AWIN, b1 = wlLo - NWIN;
    const float b2 = wlHi + NWIN, b3 = wlHi + AWIN;
    const float n1w = fmaf(span, 1.0f / 3.0f, wlLo);
    const float n2w = fmaf(span, 2.0f / 3.0f, wlLo);

    if (tid < 2) { sIdx[tid * 2] = 0x7FFFFFFF; sIdx[tid * 2 + 1] = -1; }
    __syncthreads();

    // ---- stream all lines: constants + far sums + slot stash ----
    float S0 = 0.f, S1 = 0.f, S2 = 0.f, S3 = 0.f;

    auto body = [&](int l, float lc, float am, float swv, float gwv) {
        float sigma = fex2(swv * LOG2E);
        float gamma = fex2(gwv * LOG2E);
        float amp   = fex2(am * LOG2E);
        float fg = 2.3548f * sigma;
        float fl = 2.0f * gamma;
        float fg2 = fg * fg;
        float fl2 = fl * fl;
        float poly = fg2 * fg2 * fg
                   + 2.69269f * fg2 * fg2 * fl
                   + 2.42843f * fg2 * fg  * fl2
                   + 4.47163f * fg2 * fl  * fl2
                   + 0.07842f * fg  * fl2 * fl2
                   + fl2 * fl2 * fl;
        float fr  = fl * fex2(-0.2f * flg2(poly));
        float eta = fr * (1.36603f + fr * (-0.47719f + fr * 0.11116f));
        float g2  = gamma * gamma;
        float cl  = amp * eta * gamma * 0.3183098862f;

        if (lc >= b0 && lc < b3) {
            float invs = frcp(sigma);
            int slot = l & SMASK;
            sA[slot] = make_float4(lc, g2, cl, -0.72134752f * invs * invs);
            sB[slot] = amp * (1.0f - eta) * invs * 0.39894228f;
            atomicMin(&sIdx[0], l);
            atomicMax(&sIdx[1], l);
            if (lc >= b1 && lc < b2) {
                atomicMin(&sIdx[2], l);
                atomicMax(&sIdx[3], l);
            }
        } else {
            float d0 = wlLo - lc, d1 = n1w - lc, d2 = n2w - lc, d3 = wlHi - lc;
            float e0 = fmaf(d0, d0, g2), e1 = fmaf(d1, d1, g2);
            float e2 = fmaf(d2, d2, g2), e3 = fmaf(d3, d3, g2);
            float p01 = e0 * e1, p23 = e2 * e3;
            float r   = frcp(p01 * p23);
            float r01 = r * p23, r23 = r * p01;
            S0 = fmaf(cl * e1, r01, S0);
            S1 = fmaf(cl * e0, r01, S1);
            S2 = fmaf(cl * e3, r23, S2);
            S3 = fmaf(cl * e2, r23, S3);
        }
    };

    {
        // prefetch first 4 strips (MLP ~16), then compute; rare remainder loop
        float lamv[4], av[4], swv[4], gwv[4];
        #pragma unroll
        for (int k = 0; k < 4; k++) {
            int l = tid + k * BLOCK;
            if (l < L) {
                lamv[k] = lam[l];
                av[k]   = amps[l];
                swv[k]  = sw[l];
                gwv[k]  = gw[l];
            }
        }
        #pragma unroll
        for (int k = 0; k < 4; k++) {
            int l = tid + k * BLOCK;
            if (l < L) body(l, lamv[k], av[k], swv[k], gwv[k]);
        }
        for (int l = tid + 4 * BLOCK; l < L; l += BLOCK)
            body(l, lam[l], amps[l], sw[l], gw[l]);
    }

    #pragma unroll
    for (int o = 16; o; o >>= 1) {
        S0 += __shfl_xor_sync(FULLM, S0, o);
        S1 += __shfl_xor_sync(FULLM, S1, o);
        S2 += __shfl_xor_sync(FULLM, S2, o);
        S3 += __shfl_xor_sync(FULLM, S3, o);
    }
    if (lane == 0) {
        sWredF[w]              = S0;
        sWredF[NWARPS + w]     = S1;
        sWredF[2 * NWARPS + w] = S2;
        sWredF[3 * NWARPS + w] = S3;
    }
    __syncthreads();

    int alo = sIdx[0], ahi = sIdx[1] + 1;
    if (ahi <= alo) { alo = 0; ahi = 0; }
    ahi = min(ahi, alo + STASH);
    int nlo = sIdx[2], nhi = sIdx[3] + 1;
    if (nhi <= nlo) { nlo = alo; nhi = alo; }
    nlo = max(nlo, alo); nhi = min(nhi, ahi);

    // ---- far-node reduction, lane-parallel on warps 16..19 ----
    if (w >= 16 && w < 20) {
        int node = w - 16;
        float v = (lane < NWARPS) ? sWredF[node * NWARPS + lane] : 0.f;
        #pragma unroll
        for (int o = 16; o; o >>= 1) v += __shfl_xor_sync(FULLM, v, o);
        if (lane == 0) sS[node] = v;
    }

    // ---- CTA-mid: 16 uniform nodes, warp w -> node w ----
    if (w < 16) {
        float nodeM = fmaf((float)w, span * (1.0f / 15.0f), wlLo);
        float accM = 0.f;
        for (int j = alo + lane; j < nlo; j += 32) {
            float4 a = sA[j & SMASK];
            float d = nodeM - a.x;
            accM = fmaf(a.z, frcp(fmaf(d, d, a.y)), accM);
        }
        for (int j = nhi + lane; j < ahi; j += 32) {
            float4 a = sA[j & SMASK];
            float d = nodeM - a.x;
            accM = fmaf(a.z, frcp(fmaf(d, d, a.y)), accM);
        }
        #pragma unroll
        for (int o = 16; o; o >>= 1) accM += __shfl_xor_sync(FULLM, accM, o);
        if (lane == 0) sMid[w] = accM;
    }

    // ---- per-warp near/mid over the chunk-near range ----
    float prod = 1.0f;
    float M0 = 0.f, M1 = 0.f, M2 = 0.f;
    float x0n = 0.f, x2n = 0.f;
    if (w < (CHUNK + 31) / 32) {
        x0n = __shfl_sync(FULLM, wlp, 0);
        x2n = __shfl_sync(FULLM, wlp, 31);
        const float wLo = x0n - WNWIN, wHi = x2n + WNWIN;

        int glo = nhi, ghi = nlo;
        for (int base = nlo; base < nhi; base += 32) {
            int idx = base + lane;
            bool in = (idx < nhi) && (sA[idx & SMASK].x >= wLo)
                                  && (sA[idx & SMASK].x <= wHi);
            unsigned m = __ballot_sync(FULLM, in);
            if (m) {
                glo = min(glo, base + (__ffs(m) - 1));
                ghi = max(ghi, base + (31 - __clz(m)) + 1);
            }
        }
        if (ghi < glo) { glo = nlo; ghi = nlo; }

        // warp-mid: 3 warp nodes, batched rcp, lane-strided
        const float x1n = 0.5f * (x0n + x2n);
        for (int j = nlo + lane; j < nhi; j += 32) {
            if (j >= glo && j < ghi) continue;
            float4 a = sA[j & SMASK];
            float d0 = x0n - a.x, d1 = x1n - a.x, d2 = x2n - a.x;
            float e0 = fmaf(d0, d0, a.y);
            float e1 = fmaf(d1, d1, a.y);
            float e2 = fmaf(d2, d2, a.y);
            float p01 = e0 * e1;
            float r   = frcp(p01 * e2);
            float r01 = r * e2;
            M0 = fmaf(a.z * e1, r01, M0);
            M1 = fmaf(a.z * e0, r01, M1);
            M2 = fmaf(a.z, r * p01, M2);
        }
        #pragma unroll
        for (int o = 16; o; o >>= 1) {
            M0 += __shfl_xor_sync(FULLM, M0, o);
            M1 += __shfl_xor_sync(FULLM, M1, o);
            M2 += __shfl_xor_sync(FULLM, M2, o);
        }

        // warp-near: exact voigt, dual accumulators
        float prodA = 1.0f, prodB = 1.0f;
        int j = glo;
        for (; j + 1 < ghi; j += 2) {
            float4 a0 = sA[j & SMASK];       float cg0 = sB[j & SMASK];
            float4 a1 = sA[(j + 1) & SMASK]; float cg1 = sB[(j + 1) & SMASK];
            float dd0 = wlp - a0.x, dd1 = wlp - a1.x;
            float q0 = dd0 * dd0,   q1 = dd1 * dd1;
            float v0 = fmaf(cg0, fex2(q0 * a0.w), a0.z * frcp(q0 + a0.y));
            float v1 = fmaf(cg1, fex2(q1 * a1.w), a1.z * frcp(q1 + a1.y));
            prodA = fmaf(-v0, prodA, prodA);
            prodB = fmaf(-v1, prodB, prodB);
        }
        if (j < ghi) {
            float4 a = sA[j & SMASK]; float cg = sB[j & SMASK];
            float dd = wlp - a.x;
            float q  = dd * dd;
            float v  = fmaf(cg, fex2(q * a.w), a.z * frcp(q + a.y));
            prodA = fmaf(-v, prodA, prodA);
        }
        prod = prodA * prodB;
    }

    __syncthreads();   // sMid, sS visible

    // ---- epilogue ----
    if (tid < cnt && p < npix) {
        const float ic = frcp((float)(cnt - 1));

        float s = (float)tid * (3.0f * ic);
        float sm1 = s - 1.0f, sm2 = s - 2.0f, sm3 = s - 3.0f;
        float Sfar = (sm1 * sm2 * sm3) * (-1.0f / 6.0f) * sS[0]
                   + (s   * sm2 * sm3) * ( 0.5f       ) * sS[1]
                   + (s   * sm1 * sm3) * (-0.5f       ) * sS[2]
                   + (s   * sm1 * sm2) * ( 1.0f / 6.0f) * sS[3];

        float t  = (float)tid * (15.0f * ic);
        int   i  = min(max((int)t, 1), 13);
        float x  = t - (float)i;
        float xp1 = x + 1.0f, xm1 = x - 1.0f, xm2 = x - 2.0f;
        float Smid = (-x   * xm1 * xm2 * (1.0f / 6.0f)) * sMid[i - 1]
                   + ( xp1 * xm1 * xm2 * 0.5f         ) * sMid[i]
                   + (-xp1 * x   * xm2 * 0.5f         ) * sMid[i + 1]
                   + ( xp1 * x   * xm1 * (1.0f / 6.0f)) * sMid[i + 2];

        float hw = 0.5f * (x2n - x0n);
        float u  = (wlp - x0n) * frcp(hw);
        float um1 = u - 1.0f, um2 = u - 2.0f;
        float Swm = (um1 * um2 * 0.5f) * M0
                  + (u * (2.0f - u)  ) * M1
                  + (u * um1 * 0.5f  ) * M2;

        float xw   = (wlp - 10500.0f) * (1.0f / 2500.0f);
        float polw = pa[0] + (pb[0] + pc[0] * xw) * xw;
        out[p] = prod * fex2(-(Sfar + Smid + Swm) * (float)LOG2E) * polw;
    }
}

extern "C" void kernel_launch(void* const* d_in, const int* in_sizes, int n_in,
                              void* d_out, int out_size) {
    const float* wl   = (const float*)d_in[0];
    const float* lam  = (const float*)d_in[1];
    const float* amps = (const float*)d_in[2];
    const float* sw   = (const float*)d_in[3];
    const float* gw   = (const float*)d_in[4];
    const float* pa   = (const float*)d_in[5];
    const float* pb   = (const float*)d_in[6];
    const float* pc   = (const float*)d_in[7];
    float* out = (float*)d_out;

    int npix = in_sizes[0];
    int L    = in_sizes[1];

    int nchunks = (npix + CHUNK - 1) / CHUNK;
    fused_kernel<<<nchunks, BLOCK>>>(wl, npix, L, lam, amps, sw, gw,
                                     pa, pb, pc, out);
}